// round 8
// baseline (speedup 1.0000x reference)
#include <cuda_runtime.h>
#include <math.h>

#define LDIM 4096
#define NPTS 2048
#define WPIX 640.0f
#define HPIX 480.0f

// 256-bit load with L2 evict_last hint (sm_103 requires v8.b32 for the hint).
__device__ __forceinline__ void ldg256_el(const float* __restrict__ p,
                                          float4& a, float4& b)
{
    asm volatile("ld.global.nc.L2::evict_last.v8.b32 "
                 "{%0,%1,%2,%3,%4,%5,%6,%7}, [%8];"
                 : "=f"(a.x), "=f"(a.y), "=f"(a.z), "=f"(a.w),
                   "=f"(b.x), "=f"(b.y), "=f"(b.z), "=f"(b.w)
                 : "l"(p));
}

struct Acc { float Sxx, Sxy, Syy, Sx, Sy; };

__device__ __forceinline__ void accum_f4(Acc& A, float4 v,
                                         float invW, float invH,
                                         float cx, float cy, float alpha)
{
    float sx = v.x * invW - cx;
    float sy = v.y * invH - cy;
    float r2 = sx * sx + sy * sy;
    float f  = 1.0f + alpha * r2;
    float ux = f * sx + cx;
    float uy = f * sy + cy;
    A.Sxx += ux * ux; A.Sxy += ux * uy; A.Syy += uy * uy; A.Sx += ux; A.Sy += uy;

    sx = v.z * invW - cx;
    sy = v.w * invH - cy;
    r2 = sx * sx + sy * sy;
    f  = 1.0f + alpha * r2;
    ux = f * sx + cx;
    uy = f * sy + cy;
    A.Sxx += ux * ux; A.Sxy += ux * uy; A.Syy += uy * uy; A.Sx += ux; A.Sy += uy;
}

__device__ __forceinline__ void warp_reduce(Acc& A)
{
    #pragma unroll
    for (int o = 16; o > 0; o >>= 1) {
        A.Sxx += __shfl_xor_sync(0xffffffffu, A.Sxx, o);
        A.Sxy += __shfl_xor_sync(0xffffffffu, A.Sxy, o);
        A.Syy += __shfl_xor_sync(0xffffffffu, A.Syy, o);
        A.Sx  += __shfl_xor_sync(0xffffffffu, A.Sx,  o);
        A.Sy  += __shfl_xor_sync(0xffffffffu, A.Sy,  o);
    }
}

// Solve: smallest eigenpair of M built from 5 moments; returns fit error.
__device__ __forceinline__ float solve_moments(const float* sm)
{
    float m00 =  sm[0];
    float m01 =  sm[1];
    float m11 =  sm[2];
    float m02 = -sm[3];
    float m12 = -sm[4];
    float m22 =  (float)NPTS;

    // Newton on det(M - lam I) from lam=0: monotone convergence for SPD M.
    float lam = 0.0f;
    #pragma unroll
    for (int it = 0; it < 6; it++) {
        float a00 = m00 - lam, a11 = m11 - lam, a22 = m22 - lam;
        float M0 = a11 * a22 - m12 * m12;
        float M1 = a00 * a22 - m02 * m02;
        float M2 = a00 * a11 - m01 * m01;
        float det = a00 * M0
                  - m01 * (m01 * a22 - m12 * m02)
                  + m02 * (m01 * m12 - a11 * m02);
        float dp = M0 + M1 + M2;
        lam += det / fmaxf(dp, 1e-20f);
    }

    float c00 = m00 - lam, c11 = m11 - lam, c22 = m22 - lam;

    float x0 = m01 * m12 - m02 * c11;
    float y0 = m02 * m01 - c00 * m12;
    float z0 = c00 * c11 - m01 * m01;
    float n0 = x0 * x0 + y0 * y0 + z0 * z0;

    float x1 = m01 * c22 - m02 * m12;
    float y1 = m02 * m02 - c00 * c22;
    float z1 = c00 * m12 - m01 * m02;
    float n1 = x1 * x1 + y1 * y1 + z1 * z1;

    float x2 = c11 * c22 - m12 * m12;
    float y2 = m12 * m02 - m01 * c22;
    float z2 = m01 * m12 - c11 * m02;
    float n2 = x2 * x2 + y2 * y2 + z2 * z2;

    float vx = x0, vy = y0, vz = z0, nb = n0;
    if (n1 > nb) { vx = x1; vy = y1; vz = z1; nb = n1; }
    if (n2 > nb) { vx = x2; vy = y2; vz = z2; nb = n2; }

    float vMv = m00 * vx * vx + m11 * vy * vy + m22 * vz * vz
              + 2.0f * (m01 * vx * vy + m02 * vx * vz + m12 * vy * vz);
    return vMv / (vx * vx + vy * vy);
}

// ---------------------------------------------------------------------------
// Fused kernel: one block per TWO rows (l0, l1). 128 threads, 8 front-batched
// LDG.256 per thread (32KB/block, MLP=8). Two independent moment sets; the
// two eigensolves run concurrently in warps 0 and 1.
// ---------------------------------------------------------------------------
__global__ void __launch_bounds__(128)
fused_kernel(const float* __restrict__ in,
             const float* __restrict__ center,
             const float* __restrict__ alpha_p,
             float* __restrict__ out)
{
    const int l0 = blockIdx.x * 2;
    const int t = threadIdx.x;

    const float cx = center[0];
    const float cy = center[1];
    const float alpha = alpha_p[0];
    const float invW = 1.0f / WPIX;
    const float invH = 1.0f / HPIX;

    const float* base0 = in + (size_t)l0 * (NPTS * 2);
    const float* base1 = base0 + (NPTS * 2);

    // Eight 256-bit loads, all front-batched (MLP=8).
    float4 a0, a1, a2, a3, a4, a5, a6, a7;   // row 0
    float4 b0, b1, b2, b3, b4, b5, b6, b7;   // row 1
    ldg256_el(base0 +        t * 8, a0, a1);
    ldg256_el(base0 + 1024 + t * 8, a2, a3);
    ldg256_el(base0 + 2048 + t * 8, a4, a5);
    ldg256_el(base0 + 3072 + t * 8, a6, a7);
    ldg256_el(base1 +        t * 8, b0, b1);
    ldg256_el(base1 + 1024 + t * 8, b2, b3);
    ldg256_el(base1 + 2048 + t * 8, b4, b5);
    ldg256_el(base1 + 3072 + t * 8, b6, b7);

    Acc A = {0.f, 0.f, 0.f, 0.f, 0.f};
    Acc B = {0.f, 0.f, 0.f, 0.f, 0.f};

    accum_f4(A, a0, invW, invH, cx, cy, alpha);
    accum_f4(A, a1, invW, invH, cx, cy, alpha);
    accum_f4(A, a2, invW, invH, cx, cy, alpha);
    accum_f4(A, a3, invW, invH, cx, cy, alpha);
    accum_f4(A, a4, invW, invH, cx, cy, alpha);
    accum_f4(A, a5, invW, invH, cx, cy, alpha);
    accum_f4(A, a6, invW, invH, cx, cy, alpha);
    accum_f4(A, a7, invW, invH, cx, cy, alpha);

    accum_f4(B, b0, invW, invH, cx, cy, alpha);
    accum_f4(B, b1, invW, invH, cx, cy, alpha);
    accum_f4(B, b2, invW, invH, cx, cy, alpha);
    accum_f4(B, b3, invW, invH, cx, cy, alpha);
    accum_f4(B, b4, invW, invH, cx, cy, alpha);
    accum_f4(B, b5, invW, invH, cx, cy, alpha);
    accum_f4(B, b6, invW, invH, cx, cy, alpha);
    accum_f4(B, b7, invW, invH, cx, cy, alpha);

    warp_reduce(A);
    warp_reduce(B);

    __shared__ float sm[10];
    if (t < 10) sm[t] = 0.f;
    __syncthreads();
    if ((t & 31) == 0) {
        atomicAdd(&sm[0], A.Sxx);
        atomicAdd(&sm[1], A.Sxy);
        atomicAdd(&sm[2], A.Syy);
        atomicAdd(&sm[3], A.Sx);
        atomicAdd(&sm[4], A.Sy);
        atomicAdd(&sm[5], B.Sxx);
        atomicAdd(&sm[6], B.Sxy);
        atomicAdd(&sm[7], B.Syy);
        atomicAdd(&sm[8], B.Sx);
        atomicAdd(&sm[9], B.Sy);
    }
    __syncthreads();

    // Two solves in parallel, one per warp.
    if (t == 0)  out[l0]     = solve_moments(sm);
    if (t == 32) out[l0 + 1] = solve_moments(sm + 5);
}

extern "C" void kernel_launch(void* const* d_in, const int* in_sizes, int n_in,
                              void* d_out, int out_size)
{
    const float* input  = (const float*)d_in[0];
    const float* center = (const float*)d_in[1];
    const float* alpha  = (const float*)d_in[2];
    float* out = (float*)d_out;

    fused_kernel<<<LDIM / 2, 128>>>(input, center, alpha, out);
}

// round 9
// speedup vs baseline: 1.1650x; 1.1650x over previous
#include <cuda_runtime.h>
#include <math.h>

#define LDIM 4096
#define NPTS 2048
#define WPIX 640.0f
#define HPIX 480.0f

// 256-bit load with L2 evict_last hint (sm_103 requires v8.b32 for the hint).
__device__ __forceinline__ void ldg256_el(const float* __restrict__ p,
                                          float4& a, float4& b)
{
    asm volatile("ld.global.nc.L2::evict_last.v8.b32 "
                 "{%0,%1,%2,%3,%4,%5,%6,%7}, [%8];"
                 : "=f"(a.x), "=f"(a.y), "=f"(a.z), "=f"(a.w),
                   "=f"(b.x), "=f"(b.y), "=f"(b.z), "=f"(b.w)
                 : "l"(p));
}

// ---------------------------------------------------------------------------
// Fused kernel: one block per l. 128 threads, 4 x 32B LDG.256 per thread
// (16KB per block). __launch_bounds__(128, 8) gives ptxas a 64-reg budget so
// all 4 loads can be genuinely front-batched in SASS (true MLP=4); the
// previous 32-reg compile serialized them.
// ---------------------------------------------------------------------------
__global__ void __launch_bounds__(128, 8)
fused_kernel(const float* __restrict__ in,
             const float* __restrict__ center,
             const float* __restrict__ alpha_p,
             float* __restrict__ out)
{
    const int l = blockIdx.x;
    const int t = threadIdx.x;

    const float cx = center[0];
    const float cy = center[1];
    const float alpha = alpha_p[0];
    const float invW = 1.0f / WPIX;
    const float invH = 1.0f / HPIX;

    const float* base = in + (size_t)l * (NPTS * 2);

    // Four 256-bit loads per thread, front-batched.
    float4 v0, v1, v2, v3, v4, v5, v6, v7;
    ldg256_el(base +        t * 8, v0, v1);
    ldg256_el(base + 1024 + t * 8, v2, v3);
    ldg256_el(base + 2048 + t * 8, v4, v5);
    ldg256_el(base + 3072 + t * 8, v6, v7);

    float Sxx = 0.f, Sxy = 0.f, Syy = 0.f, Sx = 0.f, Sy = 0.f;

    float4 vs[8] = {v0, v1, v2, v3, v4, v5, v6, v7};
    #pragma unroll
    for (int i = 0; i < 8; i++) {
        float4 v = vs[i];

        float sx = v.x * invW - cx;
        float sy = v.y * invH - cy;
        float r2 = sx * sx + sy * sy;
        float f  = 1.0f + alpha * r2;
        float ux = f * sx + cx;
        float uy = f * sy + cy;
        Sxx += ux * ux; Sxy += ux * uy; Syy += uy * uy; Sx += ux; Sy += uy;

        sx = v.z * invW - cx;
        sy = v.w * invH - cy;
        r2 = sx * sx + sy * sy;
        f  = 1.0f + alpha * r2;
        ux = f * sx + cx;
        uy = f * sy + cy;
        Sxx += ux * ux; Sxy += ux * uy; Syy += uy * uy; Sx += ux; Sy += uy;
    }

    #pragma unroll
    for (int o = 16; o > 0; o >>= 1) {
        Sxx += __shfl_xor_sync(0xffffffffu, Sxx, o);
        Sxy += __shfl_xor_sync(0xffffffffu, Sxy, o);
        Syy += __shfl_xor_sync(0xffffffffu, Syy, o);
        Sx  += __shfl_xor_sync(0xffffffffu, Sx,  o);
        Sy  += __shfl_xor_sync(0xffffffffu, Sy,  o);
    }

    __shared__ float sm[5];
    if (t < 5) sm[t] = 0.f;
    __syncthreads();
    if ((t & 31) == 0) {
        atomicAdd(&sm[0], Sxx);
        atomicAdd(&sm[1], Sxy);
        atomicAdd(&sm[2], Syy);
        atomicAdd(&sm[3], Sx);
        atomicAdd(&sm[4], Sy);
    }
    __syncthreads();

    if (t == 0) {
        // M = [[Sxx, Sxy, -Sx], [Sxy, Syy, -Sy], [-Sx, -Sy, N]]
        float m00 =  sm[0];
        float m01 =  sm[1];
        float m11 =  sm[2];
        float m02 = -sm[3];
        float m12 = -sm[4];
        float m22 =  (float)NPTS;

        // Newton on det(M - lam I) from lam = 0: monotone convergence for
        // SPD M with well-separated lam_min.
        float lam = 0.0f;
        #pragma unroll
        for (int it = 0; it < 6; it++) {
            float a00 = m00 - lam, a11 = m11 - lam, a22 = m22 - lam;
            float M0 = a11 * a22 - m12 * m12;
            float M1 = a00 * a22 - m02 * m02;
            float M2 = a00 * a11 - m01 * m01;
            float det = a00 * M0
                      - m01 * (m01 * a22 - m12 * m02)
                      + m02 * (m01 * m12 - a11 * m02);
            float dp = M0 + M1 + M2;           // = -p'(lam)
            lam += det / fmaxf(dp, 1e-20f);
        }

        // Eigenvector: largest cross product of rows of (M - lam I).
        float c00 = m00 - lam, c11 = m11 - lam, c22 = m22 - lam;

        float x0 = m01 * m12 - m02 * c11;
        float y0 = m02 * m01 - c00 * m12;
        float z0 = c00 * c11 - m01 * m01;
        float n0 = x0 * x0 + y0 * y0 + z0 * z0;

        float x1 = m01 * c22 - m02 * m12;
        float y1 = m02 * m02 - c00 * c22;
        float z1 = c00 * m12 - m01 * m02;
        float n1 = x1 * x1 + y1 * y1 + z1 * z1;

        float x2 = c11 * c22 - m12 * m12;
        float y2 = m12 * m02 - m01 * c22;
        float z2 = m01 * m12 - c11 * m02;
        float n2 = x2 * x2 + y2 * y2 + z2 * z2;

        float vx = x0, vy = y0, vz = z0, nbest = n0;
        if (n1 > nbest) { vx = x1; vy = y1; vz = z1; nbest = n1; }
        if (n2 > nbest) { vx = x2; vy = y2; vz = z2; nbest = n2; }

        // err = v^T M v / (vx^2 + vy^2)
        float vMv = m00 * vx * vx + m11 * vy * vy + m22 * vz * vz
                  + 2.0f * (m01 * vx * vy + m02 * vx * vz + m12 * vy * vz);
        float denom = vx * vx + vy * vy;
        out[l] = vMv / denom;
    }
}

extern "C" void kernel_launch(void* const* d_in, const int* in_sizes, int n_in,
                              void* d_out, int out_size)
{
    const float* input  = (const float*)d_in[0];
    const float* center = (const float*)d_in[1];
    const float* alpha  = (const float*)d_in[2];
    float* out = (float*)d_out;

    fused_kernel<<<LDIM, 128>>>(input, center, alpha, out);
}